// round 7
// baseline (speedup 1.0000x reference)
#include <cuda_runtime.h>

// B, N, D, L = 32, 1000, 256, 3
#define BB 32
#define NN 1000
#define DD 256
#define LL 3
#define CHUNKS 50
#define ROWS_PER_CHUNK 20          // 50 * 20 = 1000
#define TOTAL4 (BB * NN * DD / 4)  // 2,048,000 float4 per output half
#define B4 (NN * DD / 4)           // 64,000 float4 per batch
#define NRED (BB * CHUNKS)         // 1600 reduce CTAs
#define NCOPY 1000                 // 1000 copy CTAs (x 256 thr x 8 f4 = TOTAL4)

// Scratch (no device allocation allowed)
__device__ float    g_partial[NRED * DD];
__device__ float    g_v[BB * DD];
__device__ unsigned g_cnt[BB];     // monotonic; (old % CHUNKS)==CHUNKS-1 -> last

// ---------------------------------------------------------------------------
// KA: reduce CTAs + copy CTAs in one launch.
//  id < 1600 : partial mean over 20 rows (R4 shape, proven), then the LAST
//              finishing CTA of each batch runs the 3-layer GEMV inline.
//  id >= 1600: copy half  out[TOTAL4:] = nf  (independent of v; overlaps).
// ---------------------------------------------------------------------------
__global__ __launch_bounds__(256)
void kA(const float* __restrict__ nf,
        const float* __restrict__ Ws,
        const float* __restrict__ bs,
        float* __restrict__ out) {
    const int id = blockIdx.x;
    const int x = threadIdx.x;    // 0..63
    const int y = threadIdx.y;    // 0..3
    const int tid = y * 64 + x;   // 0..255

    const float4* __restrict__ nf4 = reinterpret_cast<const float4*>(nf);

    if (id < NRED) {
        // ---------------- reduce CTA ----------------
        const int b = id / CHUNKS;
        const int c = id % CHUNKS;
        const int base = (b * NN + c * ROWS_PER_CHUNK) * 64;

        // 5 front-batched LDG.128 (rows y, y+4, ..., y+16)
        const float4 a0 = nf4[base + (y +  0) * 64 + x];
        const float4 a1 = nf4[base + (y +  4) * 64 + x];
        const float4 a2 = nf4[base + (y +  8) * 64 + x];
        const float4 a3 = nf4[base + (y + 12) * 64 + x];
        const float4 a4 = nf4[base + (y + 16) * 64 + x];

        float4 s;
        s.x = (a0.x + a1.x) + (a2.x + a3.x) + a4.x;
        s.y = (a0.y + a1.y) + (a2.y + a3.y) + a4.y;
        s.z = (a0.z + a1.z) + (a2.z + a3.z) + a4.z;
        s.w = (a0.w + a1.w) + (a2.w + a3.w) + a4.w;

        __shared__ float4 sm[4][64];
        sm[y][x] = s;
        __syncthreads();
        if (y == 0) {
            float4 t = sm[0][x];
            const float4 t1 = sm[1][x], t2 = sm[2][x], t3 = sm[3][x];
            t.x += t1.x + t2.x + t3.x;
            t.y += t1.y + t2.y + t3.y;
            t.z += t1.z + t2.z + t3.z;
            t.w += t1.w + t2.w + t3.w;
            reinterpret_cast<float4*>(g_partial)[id * 64 + x] = t;
        }

        // last-arriving CTA of this batch does the GEMV (threadfence pattern)
        __shared__ unsigned s_last;
        __threadfence();
        if (tid == 0) {
            const unsigned old = atomicAdd(&g_cnt[b], 1u);
            s_last = ((old % CHUNKS) == CHUNKS - 1) ? 1u : 0u;
        }
        __syncthreads();
        if (!s_last) return;
        __threadfence();   // acquire: all partials of batch b visible

        __shared__ float sv[DD];
        {
            float acc = 0.f;
#pragma unroll 10
            for (int c2 = 0; c2 < CHUNKS; c2++)
                acc += g_partial[(b * CHUNKS + c2) * DD + tid];
            sv[tid] = acc * (1.0f / (float)NN);
        }
        __syncthreads();

#pragma unroll
        for (int l = 0; l < LL; l++) {
            const float* __restrict__ W = Ws + l * DD * DD;
            float c0 = 0.f, c1 = 0.f, c2 = 0.f, c3 = 0.f;
#pragma unroll 16
            for (int k = 0; k < DD; k += 4) {
                c0 = fmaf(sv[k + 0], W[(k + 0) * DD + tid], c0);
                c1 = fmaf(sv[k + 1], W[(k + 1) * DD + tid], c1);
                c2 = fmaf(sv[k + 2], W[(k + 2) * DD + tid], c2);
                c3 = fmaf(sv[k + 3], W[(k + 3) * DD + tid], c3);
            }
            float r = (c0 + c1) + (c2 + c3) + bs[l * DD + tid];
            __syncthreads();                   // all reads of sv done
            sv[tid] = (l < LL - 1) ? fmaxf(r, 0.f) : r;
            __syncthreads();
        }
        g_v[b * DD + tid] = sv[tid];
    } else {
        // ---------------- copy CTA: out[TOTAL4:] = nf ----------------
        float4* o4 = reinterpret_cast<float4*>(out);
        const int cid = id - NRED;             // 0..999
        const int base = cid * 2048;           // 256 thr * 8 f4

        float4 a[8];
#pragma unroll
        for (int k = 0; k < 8; k++)
            a[k] = nf4[base + k * 256 + tid];
#pragma unroll
        for (int k = 0; k < 8; k++)
            __stcs(o4 + TOTAL4 + base + k * 256 + tid, a[k]);
    }
}

// ---------------------------------------------------------------------------
// KB: add half. grid (64, B): batch on y, v[b] cached in smem (no int div).
// nf reads should be L2-hot; 4 front-batched loads per thread.
// ---------------------------------------------------------------------------
__global__ __launch_bounds__(256)
void kB(const float* __restrict__ nf, float* __restrict__ out) {
    const int b = blockIdx.y;
    const int tid = threadIdx.x;

    __shared__ float4 sv4[64];
    if (tid < 64)
        sv4[tid] = reinterpret_cast<const float4*>(g_v)[b * 64 + tid];
    __syncthreads();

    const float4* __restrict__ nf4 = reinterpret_cast<const float4*>(nf) + (size_t)b * B4;
    float4* o4 = reinterpret_cast<float4*>(out) + (size_t)b * B4;

    const int i0 = blockIdx.x * 256 + tid;     // 0..16383
    const int j1 = i0 + 16384, j2 = i0 + 32768, j3 = i0 + 49152;

    const float4 z4 = make_float4(0.f, 0.f, 0.f, 0.f);
    const float4 a0 = nf4[i0];
    const float4 a1 = nf4[j1];
    const float4 a2 = nf4[j2];
    const float4 a3 = (j3 < B4) ? nf4[j3] : z4;

#define ADD_ONE(idx, a)                                                       \
    {                                                                         \
        const float4 v = sv4[(idx) & 63];                                     \
        float4 r;                                                             \
        r.x = (a).x + v.x; r.y = (a).y + v.y;                                 \
        r.z = (a).z + v.z; r.w = (a).w + v.w;                                 \
        __stcs(o4 + (idx), r);                                                \
    }
    ADD_ONE(i0, a0)
    ADD_ONE(j1, a1)
    ADD_ONE(j2, a2)
    if (j3 < B4) ADD_ONE(j3, a3)
#undef ADD_ONE
}

extern "C" void kernel_launch(void* const* d_in, const int* in_sizes, int n_in,
                              void* d_out, int out_size) {
    // Inputs in metadata order: x (unused), node_feature, Ws, bs
    const float* nf = (const float*)d_in[1];
    const float* Ws = (const float*)d_in[2];
    const float* bs = (const float*)d_in[3];
    float* out = (float*)d_out;

    dim3 bA(64, 4);
    kA<<<NRED + NCOPY, bA>>>(nf, Ws, bs, out);   // 2600 CTAs

    dim3 gB(64, BB);                              // 2048 CTAs
    kB<<<gB, 256>>>(nf, out);
}

// round 8
// speedup vs baseline: 4.2128x; 4.2128x over previous
#include <cuda_runtime.h>

// B, N, D, L = 32, 1000, 256, 3
#define BB 32
#define NN 1000
#define DD 256
#define LL 3
#define CHUNKS 50
#define ROWS_PER_CHUNK 20         // 50 * 20 = 1000
#define TOTAL4 (BB * NN * DD / 4) // 2,048,000 float4s per output half

// Scratch (no device allocation allowed -> __device__ globals)
__device__ float g_partial[BB * CHUNKS * DD];
__device__ float g_v[BB * DD];

// ---------------------------------------------------------------------------
// K1: partial sums of node_feature over the node axis (pure read).
// grid (B, 50) = 1600 CTAs, block (64,4). Thread (x,y): float4-col x,
// row-group y, 5 front-batched LDG.128. Low regs -> high occupancy.
// Measured standalone: 8.6us.
// ---------------------------------------------------------------------------
__global__ void k_partial_mean(const float* __restrict__ nf) {
    const int b = blockIdx.x;
    const int c = blockIdx.y;
    const int x = threadIdx.x;   // 0..63
    const int y = threadIdx.y;   // 0..3

    const float4* __restrict__ nf4 = reinterpret_cast<const float4*>(nf);
    const int base = (b * NN + c * ROWS_PER_CHUNK) * 64;

    // front-batch all 5 loads (rows y, y+4, ..., y+16 of the 20-row chunk)
    const float4 a0 = nf4[base + (y +  0) * 64 + x];
    const float4 a1 = nf4[base + (y +  4) * 64 + x];
    const float4 a2 = nf4[base + (y +  8) * 64 + x];
    const float4 a3 = nf4[base + (y + 12) * 64 + x];
    const float4 a4 = nf4[base + (y + 16) * 64 + x];

    float4 s;
    s.x = (a0.x + a1.x) + (a2.x + a3.x) + a4.x;
    s.y = (a0.y + a1.y) + (a2.y + a3.y) + a4.y;
    s.z = (a0.z + a1.z) + (a2.z + a3.z) + a4.z;
    s.w = (a0.w + a1.w) + (a2.w + a3.w) + a4.w;

    __shared__ float4 sm[4][64];
    sm[y][x] = s;
    __syncthreads();
    if (y == 0) {
        float4 t = sm[0][x];
        const float4 t1 = sm[1][x], t2 = sm[2][x], t3 = sm[3][x];
        t.x += t1.x + t2.x + t3.x;
        t.y += t1.y + t2.y + t3.y;
        t.z += t1.z + t2.z + t3.z;
        t.w += t1.w + t2.w + t3.w;
        reinterpret_cast<float4*>(g_partial)[(b * CHUNKS + c) * 64 + x] = t;
    }
}

// ---------------------------------------------------------------------------
// K2: finish the mean, then 3 fused 256x256 GEMVs (+bias, ReLU between).
// One CTA per batch, 1024 threads: out-column o = t&255, K-group g = t>>8.
// (Champion R2 shape — the ONLY GEMV shape that is fast; see R7 post-mortem.)
// ---------------------------------------------------------------------------
__global__ void k_gcn_head(const float* __restrict__ Ws, const float* __restrict__ bs) {
    const int b = blockIdx.x;
    const int t = threadIdx.x;
    const int o = t & (DD - 1);
    const int g = t >> 8;       // 0..3

    __shared__ float sv[DD];
    __shared__ float part[4][DD];

    // finish mean: chunks strided over the 4 groups
    float s = 0.f;
    for (int c = g; c < CHUNKS; c += 4)
        s += g_partial[(b * CHUNKS + c) * DD + o];
    part[g][o] = s;
    __syncthreads();
    if (g == 0)
        sv[o] = (part[0][o] + part[1][o] + part[2][o] + part[3][o]) * (1.0f / (float)NN);
    __syncthreads();

#pragma unroll
    for (int l = 0; l < LL; l++) {
        const float* __restrict__ W = Ws + l * DD * DD;
        float acc = 0.f;
        const int k0 = g * 64;
#pragma unroll 8
        for (int k = k0; k < k0 + 64; k++)
            acc = fmaf(sv[k], W[k * DD + o], acc);   // coalesced, L2-resident
        part[g][o] = acc;
        __syncthreads();
        if (g == 0) {
            float r = part[0][o] + part[1][o] + part[2][o] + part[3][o] + bs[l * DD + o];
            sv[o] = (l < LL - 1) ? fmaxf(r, 0.f) : r;
        }
        __syncthreads();
    }
    if (g == 0) g_v[b * DD + o] = sv[o];
}

// ---------------------------------------------------------------------------
// K3: out[0:BND]     = node_feature + v[b,:]  (nf read L2-hot after K1)
//     out[BND:2BND]  = node_feature (copy)
// Champion version: 4 front-batched float4 loads per thread, __stcs stores.
// ---------------------------------------------------------------------------
__global__ void k_out(const float* __restrict__ nf, float* __restrict__ out) {
    const int stride = gridDim.x * blockDim.x;           // 512,000
    const int i0 = blockIdx.x * blockDim.x + threadIdx.x;

    const float4* __restrict__ nf4 = reinterpret_cast<const float4*>(nf);
    float4* o4 = reinterpret_cast<float4*>(out);

    const int ia = i0, ib = i0 + stride, ic = i0 + 2 * stride, id = i0 + 3 * stride;

    const float4 a0 = nf4[ia];
    const float4 a1 = nf4[ib];
    const float4 a2 = nf4[ic];
    const float4 a3 = nf4[id];

#define DO_ONE(idx, a)                                                        \
    {                                                                         \
        const int i = (idx) << 2;                                             \
        const int bb = i / (NN * DD);                                         \
        const int dd = i & (DD - 1);                                          \
        const float4 v = *reinterpret_cast<const float4*>(g_v + bb * DD + dd);\
        float4 r;                                                             \
        r.x = (a).x + v.x; r.y = (a).y + v.y;                                 \
        r.z = (a).z + v.z; r.w = (a).w + v.w;                                 \
        __stcs(o4 + (idx), r);                                                \
        __stcs(o4 + TOTAL4 + (idx), (a));                                     \
    }

    DO_ONE(ia, a0)
    DO_ONE(ib, a1)
    DO_ONE(ic, a2)
    DO_ONE(id, a3)
#undef DO_ONE
}

extern "C" void kernel_launch(void* const* d_in, const int* in_sizes, int n_in,
                              void* d_out, int out_size) {
    // Inputs in metadata order: x (unused), node_feature, Ws, bs
    const float* nf = (const float*)d_in[1];
    const float* Ws = (const float*)d_in[2];
    const float* bs = (const float*)d_in[3];
    float* out = (float*)d_out;

    dim3 g1(BB, CHUNKS);      // 1600 CTAs
    dim3 b1(64, 4);
    k_partial_mean<<<g1, b1>>>(nf);

    k_gcn_head<<<BB, 1024>>>(Ws, bs);

    // 2000 blocks * 256 threads * 4 float4/thread = 2,048,000 = TOTAL4 exactly
    k_out<<<2000, 256>>>(nf, out);
}